// round 8
// baseline (speedup 1.0000x reference)
#include <cuda_runtime.h>
#include <stdint.h>

#define BATCH 128
#define N_RX 34
#define IMG_H 512
#define IMG_W 512
#define N_PIX (IMG_H * IMG_W)

#define TPB 256
#define TILE_PX 1024                    // pixels per tile = TPB * 4
#define TILES_PER_GROUP 16              // per-channel span: 16 * 4KB = 64KB
#define GROUPS 16                       // 16 groups * 16KB-pixels = 262144 px

// ---------------------------------------------------------------------------
// Single fused kernel. Block = (group, batch) and covers its 64KB span in
// BOTH channel images (128KB stored per prologue). Prologue: threads 0..33
// load the batch's points once, compute p/raw/off, build per-tile occupancy
// bitmasks in smem. Streaming loop: per tile, LDS mask; fast path is two
// pure STG.128; occupied tiles merge set-bit points in ascending rx order
// (exact last-wins).
// ---------------------------------------------------------------------------
__global__ void __launch_bounds__(TPB)
vec2im_kernel(const float* __restrict__ x_vecs,
              const float* __restrict__ dw,
              const float* __restrict__ db,
              const float* __restrict__ cw,
              const float* __restrict__ cb,
              float* __restrict__ out) {
    __shared__ unsigned long long s_mask[TILES_PER_GROUP];
    __shared__ int   s_off[N_RX];
    __shared__ float s_p[N_RX];
    __shared__ float s_raw[N_RX];

    const int group = blockIdx.x;       // 0..15
    const int b     = blockIdx.y;       // 0..127
    const int tid   = threadIdx.x;

    if (tid < TILES_PER_GROUP) s_mask[tid] = 0ull;
    __syncthreads();

    // ---- Prologue: threads 0..33 each own one point of this batch ----
    if (tid < N_RX) {
        const float4 v = *reinterpret_cast<const float4*>(
            x_vecs + ((size_t)b * N_RX + tid) * 4);
        float raw  = v.x;
        float mask = (raw != 0.0f) ? 1.0f : 0.0f;
        float p    = raw * dw[tid] + mask * db[tid];
        int   cat  = (int)v.w;
        p = p * cw[cat] + mask * cb[cat];
        int xx  = (int)rintf(v.y);      // col 1 -> x
        int yy  = (int)rintf(v.z);      // col 2 -> y
        int off = yy * IMG_W + xx;
        s_off[tid] = off;
        s_p[tid]   = p;
        s_raw[tid] = raw;
        int tl = (off >> 10) - group * TILES_PER_GROUP;
        if ((unsigned)tl < (unsigned)TILES_PER_GROUP)
            atomicOr(&s_mask[tl], 1ull << tid);
    }
    __syncthreads();

    // ---- Streaming loop: 16 tiles; per tile store ch0 and ch1 float4 ----
    const int px_group0 = group * (TILES_PER_GROUP * TILE_PX);
    float4* o4_c0 = reinterpret_cast<float4*>(
                        out + (size_t)(b * 2 + 0) * N_PIX + px_group0) + tid;
    float4* o4_c1 = reinterpret_cast<float4*>(
                        out + (size_t)(b * 2 + 1) * N_PIX + px_group0) + tid;

    #pragma unroll
    for (int t = 0; t < TILES_PER_GROUP; t++) {
        unsigned long long m = s_mask[t];
        float4 a0 = make_float4(0.f, 0.f, 0.f, 0.f);   // channel 0 (p)
        float4 a1 = make_float4(0.f, 0.f, 0.f, 0.f);   // channel 1 (raw)
        if (m) {
            const int my0 = px_group0 + t * TILE_PX + tid * 4;
            do {                        // ascending rr => exact last-wins
                int rr = __ffsll((long long)m) - 1;
                m &= m - 1;
                int d = s_off[rr] - my0;
                if ((unsigned)d < 4u) {
                    float p   = s_p[rr];
                    float raw = s_raw[rr];
                    if      (d == 0) { a0.x = p; a1.x = raw; }
                    else if (d == 1) { a0.y = p; a1.y = raw; }
                    else if (d == 2) { a0.z = p; a1.z = raw; }
                    else             { a0.w = p; a1.w = raw; }
                }
            } while (m);
        }
        o4_c0[t * (TILE_PX / 4)] = a0;
        o4_c1[t * (TILE_PX / 4)] = a1;
    }
}

// ---------------------------------------------------------------------------
extern "C" void kernel_launch(void* const* d_in, const int* in_sizes, int n_in,
                              void* d_out, int out_size) {
    const float* x_vecs = (const float*)d_in[0];
    const float* dw     = (const float*)d_in[1];
    const float* db     = (const float*)d_in[2];
    const float* cw     = (const float*)d_in[3];
    const float* cb     = (const float*)d_in[4];
    float* out = (float*)d_out;

    dim3 grid(GROUPS, BATCH);           // 2048 blocks, 128KB each
    vec2im_kernel<<<grid, TPB>>>(x_vecs, dw, db, cw, cb, out);
}

// round 9
// speedup vs baseline: 1.0872x; 1.0872x over previous
#include <cuda_runtime.h>
#include <stdint.h>

#define BATCH 128
#define N_RX 34
#define IMG_H 512
#define IMG_W 512
#define N_PIX (IMG_H * IMG_W)

#define TPB 256
#define TILE_PX 1024                    // pixels per tile = TPB * 4
#define TILES_PER_GROUP 8               // 8 tiles * 4KB = 32KB per block
#define GROUPS 32                       // 32 * 8 * 1024 = 262144 = N_PIX

// ---------------------------------------------------------------------------
// Single fused kernel. Block = (group, channel, batch): 32KB contiguous span.
// Prologue: threads 0..33 load the batch's points once, compute p/raw/off,
// build per-tile occupancy bitmasks in smem. Streaming loop: per tile, LDS
// mask; fast path is a pure STG.128; occupied tiles merge set-bit points in
// ascending rx order (exact last-wins).
// Grid = 8192 blocks -> ~6.9 waves at occ 8 -> <2% tail loss (vs 13.5% at
// 4096/2048 blocks in R7/R8).
// ---------------------------------------------------------------------------
__global__ void __launch_bounds__(TPB)
vec2im_kernel(const float* __restrict__ x_vecs,
              const float* __restrict__ dw,
              const float* __restrict__ db,
              const float* __restrict__ cw,
              const float* __restrict__ cb,
              float* __restrict__ out) {
    __shared__ unsigned long long s_mask[TILES_PER_GROUP];
    __shared__ int   s_off[N_RX];
    __shared__ float s_val[N_RX];

    const int group = blockIdx.x;       // 0..31
    const int ch    = blockIdx.y;       // 0..1
    const int b     = blockIdx.z;       // 0..127
    const int tid   = threadIdx.x;

    if (tid < TILES_PER_GROUP) s_mask[tid] = 0ull;
    __syncthreads();

    // ---- Prologue: threads 0..33 each own one point of this batch ----
    if (tid < N_RX) {
        const float4 v = *reinterpret_cast<const float4*>(
            x_vecs + ((size_t)b * N_RX + tid) * 4);
        float raw  = v.x;
        float mask = (raw != 0.0f) ? 1.0f : 0.0f;
        float p    = raw * dw[tid] + mask * db[tid];
        int   cat  = (int)v.w;
        p = p * cw[cat] + mask * cb[cat];
        int xx  = (int)rintf(v.y);      // col 1 -> x
        int yy  = (int)rintf(v.z);      // col 2 -> y
        int off = yy * IMG_W + xx;
        s_off[tid] = off;
        s_val[tid] = ch ? raw : p;
        int tl = (off >> 10) - group * TILES_PER_GROUP;
        if ((unsigned)tl < (unsigned)TILES_PER_GROUP)
            atomicOr(&s_mask[tl], 1ull << tid);
    }
    __syncthreads();

    // ---- Streaming loop: 8 tiles x 4KB, one float4 per thread per tile ----
    const int px_group0 = group * (TILES_PER_GROUP * TILE_PX);
    float4* o4 = reinterpret_cast<float4*>(
                     out + (size_t)(b * 2 + ch) * N_PIX + px_group0) + tid;

    #pragma unroll
    for (int t = 0; t < TILES_PER_GROUP; t++) {
        unsigned long long m = s_mask[t];
        float4 acc = make_float4(0.f, 0.f, 0.f, 0.f);
        if (m) {
            const int my0 = px_group0 + t * TILE_PX + tid * 4;
            do {                        // ascending rr => exact last-wins
                int rr = __ffsll((long long)m) - 1;
                m &= m - 1;
                int d = s_off[rr] - my0;
                if ((unsigned)d < 4u) {
                    float val = s_val[rr];
                    if      (d == 0) acc.x = val;
                    else if (d == 1) acc.y = val;
                    else if (d == 2) acc.z = val;
                    else             acc.w = val;
                }
            } while (m);
        }
        o4[t * (TILE_PX / 4)] = acc;
    }
}

// ---------------------------------------------------------------------------
extern "C" void kernel_launch(void* const* d_in, const int* in_sizes, int n_in,
                              void* d_out, int out_size) {
    const float* x_vecs = (const float*)d_in[0];
    const float* dw     = (const float*)d_in[1];
    const float* db     = (const float*)d_in[2];
    const float* cw     = (const float*)d_in[3];
    const float* cb     = (const float*)d_in[4];
    float* out = (float*)d_out;

    dim3 grid(GROUPS, 2, BATCH);        // 8192 blocks, 32KB each
    vec2im_kernel<<<grid, TPB>>>(x_vecs, dw, db, cw, cb, out);
}

// round 10
// speedup vs baseline: 1.1446x; 1.0528x over previous
#include <cuda_runtime.h>
#include <stdint.h>

#define BATCH 128
#define N_RX 34
#define IMG_H 512
#define IMG_W 512
#define N_PIX (IMG_H * IMG_W)

#define TPB 256
#define TILE_PX 1024                    // pixels per tile = TPB * 4
#define TILES_PER_GROUP 4               // 4 tiles * 4KB = 16KB per block
#define SPAN_PX (TILES_PER_GROUP * TILE_PX)   // 4096 pixels
#define GROUPS 64                       // 64 * 4096 = 262144 = N_PIX

// ---------------------------------------------------------------------------
// Zero-first, fixup-after. Per block (group, channel, batch):
//   1) threads 0..33 issue their point LDG (consumed only after streaming)
//   2) all threads stream 4 unconditional STG.128 zeros (nothing in front)
//   3) __syncthreads() -- orders fixup stores after zero stores (same-address,
//      CTA scope)
//   4) threads 0..33: compute p/raw/off; owner of a point in this span writes
//      it directly, with a smem suppress-scan for exact last-wins dedup.
// ---------------------------------------------------------------------------
__global__ void __launch_bounds__(TPB)
vec2im_kernel(const float* __restrict__ x_vecs,
              const float* __restrict__ dw,
              const float* __restrict__ db,
              const float* __restrict__ cw,
              const float* __restrict__ cb,
              float* __restrict__ out) {
    __shared__ int s_off[N_RX];

    const int group = blockIdx.x;       // 0..63
    const int ch    = blockIdx.y;       // 0..1
    const int b     = blockIdx.z;       // 0..127
    const int tid   = threadIdx.x;

    // ---- (1) issue point + weight loads early (no consumption yet) ----
    float4 v;
    float w_dw = 0.f, w_db = 0.f;
    if (tid < N_RX) {
        v    = *reinterpret_cast<const float4*>(
                   x_vecs + ((size_t)b * N_RX + tid) * 4);
        w_dw = dw[tid];
        w_db = db[tid];
    }

    // ---- (2) pure streaming: 4 x STG.128 of zeros, no dependencies ----
    const int px_group0 = group * SPAN_PX;
    float4* o4 = reinterpret_cast<float4*>(
                     out + (size_t)(b * 2 + ch) * N_PIX + px_group0) + tid;
    const float4 z = make_float4(0.f, 0.f, 0.f, 0.f);
    #pragma unroll
    for (int t = 0; t < TILES_PER_GROUP; t++) {
        o4[t * (TILE_PX / 4)] = z;
    }

    // ---- (3) compute + publish offsets, then order fixup after zeros ----
    float p = 0.f, raw = 0.f;
    int off = -1;
    if (tid < N_RX) {
        raw = v.x;
        float mask = (raw != 0.0f) ? 1.0f : 0.0f;
        p = raw * w_dw + mask * w_db;
        int cat = (int)v.w;
        p = p * cw[cat] + mask * cb[cat];
        int xx = (int)rintf(v.y);       // col 1 -> x
        int yy = (int)rintf(v.z);       // col 2 -> y
        off = yy * IMG_W + xx;
        s_off[tid] = off;
    }
    __syncthreads();

    // ---- (4) fixup: only the block owning this point's span writes ----
    if (tid < N_RX) {
        int d = off - px_group0;
        if ((unsigned)d < (unsigned)SPAN_PX) {
            // Last-wins: suppress if any LATER rx hits the same pixel.
            bool write = true;
            #pragma unroll
            for (int rr = 0; rr < N_RX; rr++) {
                if (rr > tid && s_off[rr] == off) write = false;
            }
            if (write) {
                out[(size_t)(b * 2 + ch) * N_PIX + off] = ch ? raw : p;
            }
        }
    }
}

// ---------------------------------------------------------------------------
extern "C" void kernel_launch(void* const* d_in, const int* in_sizes, int n_in,
                              void* d_out, int out_size) {
    const float* x_vecs = (const float*)d_in[0];
    const float* dw     = (const float*)d_in[1];
    const float* db     = (const float*)d_in[2];
    const float* cw     = (const float*)d_in[3];
    const float* cb     = (const float*)d_in[4];
    float* out = (float*)d_out;

    dim3 grid(GROUPS, 2, BATCH);        // 16384 blocks, 16KB each
    vec2im_kernel<<<grid, TPB>>>(x_vecs, dw, db, cw, cb, out);
}